// round 16
// baseline (speedup 1.0000x reference)
#include <cuda_runtime.h>
#include <cuda.h>
#include <cstdint>

// QuantizedLinear via mma.sync int8 (plain PTX, works on compute_103 target;
// tcgen05 is unavailable: harness compiles PTX without the 'a' suffix).
//
//   y[b,o] = scale[o] * sum_k x[b,k]*W[o,k] + bias[o]
//   x f32 [16,4096], W int32 [11008,4096] (int8-range), out f32 [16,11008].
//
// Weight trick: W int32 = LE bytes [w, signfill x3]. TMA streams raw W to
// smem (SW128); each lane PRMT-packs byte0 of 4 words -> 1 reg of 4 int8
// (exact, zero arithmetic conversion). mma.sync.m16n8k32.s8 does the math.
//
// Activations: two-level int8 quantization per batch row (q1 + residual q2,
// s2 = s1/127) -> rel_err ~1e-4 << 1e-3. N = 32 = 16 batches x 2 levels.
//
// GEMM: 172 CTAs x (M=64), K=4096 int8 in 128 chunks of 32 (=128B raw W),
// 8-stage TMA+mbarrier pipeline (74KB in flight/CTA) -> DRAM-bound (~22.5us
// floor for the 180MB weight stream).

#define IN_F    4096
#define OUT_F   11008
#define BATCH   16
#define MTILE   64
#define KCH     128                 // k-chunks (32 int8 k each)
#define NST     8
#define A_ST    (MTILE * 128)       // 8192 B raw W per stage
#define B_ST    (32 * 32)           // 1024 B packed q per stage
#define ST      (A_ST + B_ST)       // 9216
#define SMEM_TOTAL (NST * ST + NST * 16)

#define SWZ(o)  ((o) ^ (((o) >> 3) & 0x70))

__device__ float g_s[32];                                 // s1[16], s2[16]
__device__ __align__(16) unsigned char g_B[32 * IN_F];    // packed q, 128 KB

// ---------------- helpers ----------------
__device__ __forceinline__ uint32_t smem_u32(const void* p) {
    uint32_t a;
    asm("{ .reg .u64 t; cvta.to.shared.u64 t, %1; cvt.u32.u64 %0, t; }"
        : "=r"(a) : "l"(p));
    return a;
}
__device__ __forceinline__ void mbar_init(uint32_t a, uint32_t cnt) {
    asm volatile("mbarrier.init.shared.b64 [%0], %1;" :: "r"(a), "r"(cnt) : "memory");
}
__device__ __forceinline__ void mbar_expect_tx(uint32_t a, uint32_t bytes) {
    asm volatile("mbarrier.arrive.expect_tx.shared.b64 _, [%0], %1;"
                 :: "r"(a), "r"(bytes) : "memory");
}
__device__ __forceinline__ void mbar_arrive(uint32_t a) {
    asm volatile("mbarrier.arrive.shared.b64 _, [%0];" :: "r"(a) : "memory");
}
__device__ __forceinline__ void mbar_wait(uint32_t a, uint32_t ph) {
    uint32_t done;
    asm volatile(
        "{\n\t.reg .pred p;\n\t"
        "mbarrier.try_wait.parity.acquire.cta.shared::cta.b64 p, [%1], %2;\n\t"
        "selp.b32 %0, 1, 0, p;\n\t}"
        : "=r"(done) : "r"(a), "r"(ph) : "memory");
    if (!done) {
        asm volatile(
            "{\n\t.reg .pred P1;\n\t"
            "W_%=:\n\t"
            "mbarrier.try_wait.parity.acquire.cta.shared::cta.b64 P1, [%0], %1, 0x989680;\n\t"
            "@P1 bra.uni D_%=;\n\t"
            "bra.uni W_%=;\n\t"
            "D_%=:\n\t}"
            :: "r"(a), "r"(ph) : "memory");
    }
}
__device__ __forceinline__ void tma_ld_2d(uint32_t dst, const CUtensorMap* m,
                                          int cx, int cy, uint32_t mbar) {
    asm volatile(
        "cp.async.bulk.tensor.2d.shared::cta.global.tile.mbarrier::complete_tx::bytes "
        "[%0], [%1, {%2, %3}], [%4];"
        :: "r"(dst), "l"(m), "r"(cx), "r"(cy), "r"(mbar) : "memory");
}
__device__ __forceinline__ uint32_t prmt(uint32_t a, uint32_t b, uint32_t s) {
    uint32_t r;
    asm("prmt.b32 %0, %1, %2, %3;" : "=r"(r) : "r"(a), "r"(b), "r"(s));
    return r;
}
// LDS.128 of 4 raw W words -> 1 reg of 4 packed int8 (byte0 of each word).
__device__ __forceinline__ uint32_t ld_pack(uint32_t addr) {
    uint32_t w0, w1, w2, w3;
    asm volatile("ld.shared.v4.b32 {%0,%1,%2,%3}, [%4];"
                 : "=r"(w0), "=r"(w1), "=r"(w2), "=r"(w3) : "r"(addr));
    return prmt(prmt(w0, w1, 0x0040), prmt(w2, w3, 0x0040), 0x5410);
}
__device__ __forceinline__ uint32_t lds32(uint32_t addr) {
    uint32_t r;
    asm volatile("ld.shared.b32 %0, [%1];" : "=r"(r) : "r"(addr));
    return r;
}
__device__ __forceinline__ void mma_s8(uint32_t* c, const uint32_t* a,
                                       uint32_t b0, uint32_t b1) {
    asm volatile(
        "mma.sync.aligned.m16n8k32.row.col.s32.s8.s8.s32 "
        "{%0,%1,%2,%3}, {%4,%5,%6,%7}, {%8,%9}, {%0,%1,%2,%3};"
        : "+r"(c[0]), "+r"(c[1]), "+r"(c[2]), "+r"(c[3])
        : "r"(a[0]), "r"(a[1]), "r"(a[2]), "r"(a[3]), "r"(b0), "r"(b1));
}

// ---------------- K1: per-batch absmax -> scales ----------------
__global__ void absmax_k(const float4* __restrict__ X) {
    const int w = threadIdx.x >> 5, lane = threadIdx.x & 31;   // warp w = row w
    float m = 0.f;
    for (int i = lane; i < IN_F / 4; i += 32) {
        const float4 v = X[w * (IN_F / 4) + i];
        m = fmaxf(m, fmaxf(fmaxf(fabsf(v.x), fabsf(v.y)),
                           fmaxf(fabsf(v.z), fabsf(v.w))));
    }
#pragma unroll
    for (int o = 16; o; o >>= 1) m = fmaxf(m, __shfl_xor_sync(~0u, m, o));
    if (lane == 0) {
        m = fmaxf(m, 1e-20f);
        g_s[w]      = m / 127.f;      // s1
        g_s[16 + w] = m / 16129.f;    // s2 = s1/127
    }
}

// ---------------- K2: two-level quantize, packed int8 ----------------
__global__ void quant_k(const float4* __restrict__ X) {
    const int idx = blockIdx.x * blockDim.x + threadIdx.x;   // [0, 16*1024)
    const int b  = idx >> 10;
    const int kq = idx & 1023;
    const float s1 = g_s[b];
    const float i1 = 1.f / s1;
    const float i2 = 127.f * i1;
    const float4 v = X[b * (IN_F / 4) + kq];

    const int q1x = __float2int_rn(v.x * i1), q1y = __float2int_rn(v.y * i1);
    const int q1z = __float2int_rn(v.z * i1), q1w = __float2int_rn(v.w * i1);
    const float rx = fmaf(-s1, (float)q1x, v.x), ry = fmaf(-s1, (float)q1y, v.y);
    const float rz = fmaf(-s1, (float)q1z, v.z), rw = fmaf(-s1, (float)q1w, v.w);
    const int q2x = __float2int_rn(rx * i2), q2y = __float2int_rn(ry * i2);
    const int q2z = __float2int_rn(rz * i2), q2w = __float2int_rn(rw * i2);

    const uint32_t p1 = (q1x & 0xFF) | ((q1y & 0xFF) << 8)
                      | ((q1z & 0xFF) << 16) | ((uint32_t)(q1w & 0xFF) << 24);
    const uint32_t p2 = (q2x & 0xFF) | ((q2y & 0xFF) << 8)
                      | ((q2z & 0xFF) << 16) | ((uint32_t)(q2w & 0xFF) << 24);
    uint32_t* Bw = reinterpret_cast<uint32_t*>(g_B);
    Bw[b        * 1024 + kq] = p1;
    Bw[(16 + b) * 1024 + kq] = p2;
}

// ---------------- K3: int8 mma.sync GEMM ----------------
__global__ void __launch_bounds__(128, 2)
qgemm(const __grid_constant__ CUtensorMap tma_a,
      const __grid_constant__ CUtensorMap tma_b,
      const float* __restrict__ scale,
      const float* __restrict__ bias,
      float* __restrict__ out)
{
    extern __shared__ __align__(1024) char smem[];
    const uint32_t sbase = smem_u32(smem);
    const uint32_t mb    = sbase + NST * ST;   // full[s]=+s*16, empty[s]=+s*16+8

    const int tid  = threadIdx.x, lane = tid & 31, warp = tid >> 5;
    const int g    = lane >> 2,   tig  = lane & 3;
    const int o_base = blockIdx.x * MTILE;

    if (tid == 0) {
        for (int s = 0; s < NST; ++s) {
            mbar_init(mb + s * 16, 1);         // full: tx-based
            mbar_init(mb + s * 16 + 8, 128);   // empty: all threads arrive
        }
    }
    __syncthreads();

    // Prologue: fill all 8 stages.
    if (tid == 0) {
        for (int t = 0; t < NST; ++t) {
            mbar_expect_tx(mb + t * 16, ST);
            tma_ld_2d(sbase + t * ST,        &tma_a, t * 128, o_base, mb + t * 16);
            tma_ld_2d(sbase + t * ST + A_ST, &tma_b, t * 32,  0,      mb + t * 16);
        }
    }

    // Per-lane invariant smem offsets.
    const int row0 = warp * 16 + g;                    // local M row (a0/a2)
    const uint32_t oA0 = SWZ(row0 * 128 + tig * 16);
    const uint32_t oA1 = SWZ((row0 + 8) * 128 + tig * 16);
    const uint32_t oA2 = SWZ(row0 * 128 + 64 + tig * 16);
    const uint32_t oA3 = SWZ((row0 + 8) * 128 + 64 + tig * 16);
    uint32_t oB[4];
#pragma unroll
    for (int f = 0; f < 4; ++f)
        oB[f] = A_ST + (f * 8 + g) * 32 + tig * 4;     // b0; b1 = +16

    uint32_t acc[4][4];
#pragma unroll
    for (int f = 0; f < 4; ++f)
#pragma unroll
        for (int r = 0; r < 4; ++r) acc[f][r] = 0u;

#pragma unroll 1
    for (int t = 0; t < KCH; ++t) {
        const int s = t & (NST - 1);
        const uint32_t ph = (uint32_t)((t >> 3) & 1);
        mbar_wait(mb + s * 16, ph);

        const uint32_t base = sbase + s * ST;
        uint32_t a[4];
        a[0] = ld_pack(base + oA0);
        a[1] = ld_pack(base + oA1);
        a[2] = ld_pack(base + oA2);
        a[3] = ld_pack(base + oA3);
#pragma unroll
        for (int f = 0; f < 4; ++f) {
            const uint32_t b0 = lds32(base + oB[f]);
            const uint32_t b1 = lds32(base + oB[f] + 16);
            mma_s8(acc[f], a, b0, b1);
        }

        mbar_arrive(mb + s * 16 + 8);
        if (tid == 0 && t < KCH - NST) {
            mbar_wait(mb + s * 16 + 8, ph);            // all 128 done reading
            mbar_expect_tx(mb + s * 16, ST);
            const int tn = t + NST;
            tma_ld_2d(base,        &tma_a, tn * 128, o_base, mb + s * 16);
            tma_ld_2d(base + A_ST, &tma_b, tn * 32,  0,      mb + s * 16);
        }
    }

    // Epilogue. D frag f (n = f*8+g'..): c0 row g col tig*2, c1 col +1,
    // c2/c3 row g+8. Level pair: frag f and f+2 (n and n+16).
    const int o0 = o_base + warp * 16 + g;
    const int o1 = o0 + 8;
    const float sc0 = scale[o0], bi0 = bias[o0];
    const float sc1 = scale[o1], bi1 = bias[o1];
#pragma unroll
    for (int f = 0; f < 2; ++f) {
#pragma unroll
        for (int j = 0; j < 2; ++j) {
            const int b  = f * 8 + tig * 2 + j;
            const float s1 = g_s[b], s2 = g_s[16 + b];
            const float v0 = s1 * (float)(int)acc[f][j]
                           + s2 * (float)(int)acc[f + 2][j];
            const float v1 = s1 * (float)(int)acc[f][j + 2]
                           + s2 * (float)(int)acc[f + 2][j + 2];
            out[b * OUT_F + o0] = sc0 * v0 + bi0;
            out[b * OUT_F + o1] = sc1 * v1 + bi1;
        }
    }
}

// ---------------- host ----------------
typedef CUresult (*TmaEncodeFn)(
    CUtensorMap*, CUtensorMapDataType, cuuint32_t, void*,
    const cuuint64_t*, const cuuint64_t*, const cuuint32_t*, const cuuint32_t*,
    CUtensorMapInterleave, CUtensorMapSwizzle, CUtensorMapL2promotion,
    CUtensorMapFloatOOBfill);

extern "C" void kernel_launch(void* const* d_in, const int* in_sizes, int n_in,
                              void* d_out, int out_size) {
    // metadata order: x (f32), weight_int8 (int32), weight_scale (f32), bias (f32)
    const float4* X     = (const float4*)d_in[0];
    void*         W     = (void*)d_in[1];
    const float*  scale = (const float*)d_in[2];
    const float*  bias  = (const float*)d_in[3];
    float*        out   = (float*)d_out;
    (void)in_sizes; (void)n_in; (void)out_size;

    void* bptr = nullptr;
    cudaGetSymbolAddress(&bptr, g_B);

    TmaEncodeFn enc = nullptr;
    cudaDriverEntryPointQueryResult qr;
    cudaGetDriverEntryPointByVersion("cuTensorMapEncodeTiled", (void**)&enc,
                                     12000, cudaEnableDefault, &qr);

    CUtensorMap ta, tb;
    {   // A: raw W bytes [16384, 11008], box [128, 64], SW128
        cuuint64_t dims[2]   = {(cuuint64_t)IN_F * 4, OUT_F};
        cuuint64_t stride[1] = {(cuuint64_t)IN_F * 4};
        cuuint32_t box[2]    = {128, MTILE};
        cuuint32_t es[2]     = {1, 1};
        enc(&ta, CU_TENSOR_MAP_DATA_TYPE_UINT8, 2, W, dims, stride, box, es,
            CU_TENSOR_MAP_INTERLEAVE_NONE, CU_TENSOR_MAP_SWIZZLE_128B,
            CU_TENSOR_MAP_L2_PROMOTION_L2_128B, CU_TENSOR_MAP_FLOAT_OOB_FILL_NONE);
    }
    {   // B: packed q [4096, 32], box [32, 32], no swizzle
        cuuint64_t dims[2]   = {IN_F, 32};
        cuuint64_t stride[1] = {IN_F};
        cuuint32_t box[2]    = {32, 32};
        cuuint32_t es[2]     = {1, 1};
        enc(&tb, CU_TENSOR_MAP_DATA_TYPE_UINT8, 2, bptr, dims, stride, box, es,
            CU_TENSOR_MAP_INTERLEAVE_NONE, CU_TENSOR_MAP_SWIZZLE_NONE,
            CU_TENSOR_MAP_L2_PROMOTION_L2_128B, CU_TENSOR_MAP_FLOAT_OOB_FILL_NONE);
    }

    absmax_k<<<1, 512>>>(X);
    quant_k<<<BATCH * (IN_F / 4) / 256, 256>>>(X);

    cudaFuncSetAttribute(qgemm, cudaFuncAttributeMaxDynamicSharedMemorySize, SMEM_TOTAL);
    qgemm<<<OUT_F / MTILE, 128, SMEM_TOTAL>>>(ta, tb, scale, bias, out);
}

// round 17
// speedup vs baseline: 1.1748x; 1.1748x over previous
#include <cuda_runtime.h>
#include <cuda.h>
#include <cstdint>

// QuantizedLinear via mma.sync int8 (plain PTX; tcgen05 unavailable on the
// harness's compute_103 PTX target).
//
//   y[b,o] = scale[o] * sum_k x[b,k]*W[o,k] + bias[o]
//   x f32 [16,4096], W int32 [11008,4096] (int8-range), out f32 [16,11008].
//
// Weight trick: W int32 = LE bytes [w, signfill x3]. TMA streams raw W into
// SW128 smem; lanes PRMT-pack byte0 of 4 words -> 1 reg of 4 int8 (exact).
// Activations: two-level int8 quantization (q1 + residual q2, s2=s1/127)
// -> rel_err ~7e-5. N = 32 = 16 batches x 2 levels.
//
// R16 changes vs R15 (68.2us):
//   - prep fused into ONE 16-CTA kernel (absmax_k was 8us single-CTA!).
//   - K-chunk doubled to 64 int8 (256B raw W/row), 6-stage pipeline:
//     halves mbarrier-wait / arrive / TMA-request counts per byte.
//   - (2 launches/replay -> ncu -s5 now lands on qgemm for evidence.)

#define IN_F    4096
#define OUT_F   11008
#define BATCH   16
#define MTILE   64
#define KCH     64                  // chunks of 64 int8 k (256B raw W/row)
#define NST     6
#define A_ST    (MTILE * 256)       // 16384 B raw W per stage
#define B_ST    (32 * 64)           // 2048 B packed q per stage
#define ST      (A_ST + B_ST)       // 18432
#define SMEM_TOTAL (NST * ST + NST * 16)

#define SWZ(o)  ((o) ^ (((o) >> 3) & 0x70))

__device__ float g_s[32];                                 // s1[16], s2[16]
__device__ __align__(16) unsigned char g_B[32 * IN_F];    // packed q, 128 KB

// ---------------- helpers ----------------
__device__ __forceinline__ uint32_t smem_u32(const void* p) {
    uint32_t a;
    asm("{ .reg .u64 t; cvta.to.shared.u64 t, %1; cvt.u32.u64 %0, t; }"
        : "=r"(a) : "l"(p));
    return a;
}
__device__ __forceinline__ void mbar_init(uint32_t a, uint32_t cnt) {
    asm volatile("mbarrier.init.shared.b64 [%0], %1;" :: "r"(a), "r"(cnt) : "memory");
}
__device__ __forceinline__ void mbar_expect_tx(uint32_t a, uint32_t bytes) {
    asm volatile("mbarrier.arrive.expect_tx.shared.b64 _, [%0], %1;"
                 :: "r"(a), "r"(bytes) : "memory");
}
__device__ __forceinline__ void mbar_arrive(uint32_t a) {
    asm volatile("mbarrier.arrive.shared.b64 _, [%0];" :: "r"(a) : "memory");
}
__device__ __forceinline__ void mbar_wait(uint32_t a, uint32_t ph) {
    uint32_t done;
    asm volatile(
        "{\n\t.reg .pred p;\n\t"
        "mbarrier.try_wait.parity.acquire.cta.shared::cta.b64 p, [%1], %2;\n\t"
        "selp.b32 %0, 1, 0, p;\n\t}"
        : "=r"(done) : "r"(a), "r"(ph) : "memory");
    if (!done) {
        asm volatile(
            "{\n\t.reg .pred P1;\n\t"
            "W_%=:\n\t"
            "mbarrier.try_wait.parity.acquire.cta.shared::cta.b64 P1, [%0], %1, 0x989680;\n\t"
            "@P1 bra.uni D_%=;\n\t"
            "bra.uni W_%=;\n\t"
            "D_%=:\n\t}"
            :: "r"(a), "r"(ph) : "memory");
    }
}
__device__ __forceinline__ void tma_ld_2d(uint32_t dst, const CUtensorMap* m,
                                          int cx, int cy, uint32_t mbar) {
    asm volatile(
        "cp.async.bulk.tensor.2d.shared::cta.global.tile.mbarrier::complete_tx::bytes "
        "[%0], [%1, {%2, %3}], [%4];"
        :: "r"(dst), "l"(m), "r"(cx), "r"(cy), "r"(mbar) : "memory");
}
__device__ __forceinline__ uint32_t prmt(uint32_t a, uint32_t b, uint32_t s) {
    uint32_t r;
    asm("prmt.b32 %0, %1, %2, %3;" : "=r"(r) : "r"(a), "r"(b), "r"(s));
    return r;
}
// LDS.128 of 4 raw W words -> 1 reg of 4 packed int8 (byte0 of each word).
__device__ __forceinline__ uint32_t ld_pack(uint32_t addr) {
    uint32_t w0, w1, w2, w3;
    asm volatile("ld.shared.v4.b32 {%0,%1,%2,%3}, [%4];"
                 : "=r"(w0), "=r"(w1), "=r"(w2), "=r"(w3) : "r"(addr));
    return prmt(prmt(w0, w1, 0x0040), prmt(w2, w3, 0x0040), 0x5410);
}
__device__ __forceinline__ uint32_t lds32(uint32_t addr) {
    uint32_t r;
    asm volatile("ld.shared.b32 %0, [%1];" : "=r"(r) : "r"(addr));
    return r;
}
__device__ __forceinline__ void mma_s8(uint32_t* c, const uint32_t* a,
                                       uint32_t b0, uint32_t b1) {
    asm volatile(
        "mma.sync.aligned.m16n8k32.row.col.s32.s8.s8.s32 "
        "{%0,%1,%2,%3}, {%4,%5,%6,%7}, {%8,%9}, {%0,%1,%2,%3};"
        : "+r"(c[0]), "+r"(c[1]), "+r"(c[2]), "+r"(c[3])
        : "r"(a[0]), "r"(a[1]), "r"(a[2]), "r"(a[3]), "r"(b0), "r"(b1));
}

// ---------------- K1: fused absmax + two-level quantize ----------------
// One CTA per batch row: block-reduce absmax, broadcast scale, quantize.
__global__ void __launch_bounds__(256)
prep_k(const float4* __restrict__ X) {
    __shared__ float wmax[8];
    __shared__ float s_s1;
    const int b   = blockIdx.x;
    const int tid = threadIdx.x;
    const int lane = tid & 31, warp = tid >> 5;

    float m = 0.f;
#pragma unroll
    for (int i = 0; i < 4; ++i) {
        const float4 v = X[b * 1024 + i * 256 + tid];
        m = fmaxf(m, fmaxf(fmaxf(fabsf(v.x), fabsf(v.y)),
                           fmaxf(fabsf(v.z), fabsf(v.w))));
    }
#pragma unroll
    for (int o = 16; o; o >>= 1) m = fmaxf(m, __shfl_xor_sync(~0u, m, o));
    if (lane == 0) wmax[warp] = m;
    __syncthreads();
    if (tid == 0) {
        float mm = wmax[0];
#pragma unroll
        for (int w = 1; w < 8; ++w) mm = fmaxf(mm, wmax[w]);
        mm = fmaxf(mm, 1e-20f);
        g_s[b]      = mm / 127.f;     // s1
        g_s[16 + b] = mm / 16129.f;   // s2 = s1/127
        s_s1 = mm / 127.f;
    }
    __syncthreads();

    const float s1 = s_s1;
    const float i1 = 1.f / s1;
    const float i2 = 127.f * i1;
    uint32_t* Bw = reinterpret_cast<uint32_t*>(g_B);
#pragma unroll
    for (int i = 0; i < 4; ++i) {
        const int kq = i * 256 + tid;
        const float4 v = X[b * 1024 + kq];   // L2 hit (just read)
        const int q1x = __float2int_rn(v.x * i1), q1y = __float2int_rn(v.y * i1);
        const int q1z = __float2int_rn(v.z * i1), q1w = __float2int_rn(v.w * i1);
        const float rx = fmaf(-s1, (float)q1x, v.x), ry = fmaf(-s1, (float)q1y, v.y);
        const float rz = fmaf(-s1, (float)q1z, v.z), rw = fmaf(-s1, (float)q1w, v.w);
        const int q2x = __float2int_rn(rx * i2), q2y = __float2int_rn(ry * i2);
        const int q2z = __float2int_rn(rz * i2), q2w = __float2int_rn(rw * i2);
        Bw[b * 1024 + kq] = (q1x & 0xFF) | ((q1y & 0xFF) << 8)
                          | ((q1z & 0xFF) << 16) | ((uint32_t)(q1w & 0xFF) << 24);
        Bw[(16 + b) * 1024 + kq] = (q2x & 0xFF) | ((q2y & 0xFF) << 8)
                          | ((q2z & 0xFF) << 16) | ((uint32_t)(q2w & 0xFF) << 24);
    }
}

// ---------------- K2: int8 mma.sync GEMM ----------------
__global__ void __launch_bounds__(128, 2)
qgemm(const __grid_constant__ CUtensorMap tma_a,
      const __grid_constant__ CUtensorMap tma_b,
      const float* __restrict__ scale,
      const float* __restrict__ bias,
      float* __restrict__ out)
{
    extern __shared__ __align__(1024) char smem[];
    const uint32_t sbase = smem_u32(smem);
    const uint32_t mb    = sbase + NST * ST;   // full[s]=+s*16, empty[s]=+s*16+8

    const int tid  = threadIdx.x, lane = tid & 31, warp = tid >> 5;
    const int g    = lane >> 2,   tig  = lane & 3;
    const int o_base = blockIdx.x * MTILE;

    if (tid == 0) {
        for (int s = 0; s < NST; ++s) {
            mbar_init(mb + s * 16, 1);         // full: tx-based
            mbar_init(mb + s * 16 + 8, 128);   // empty: all threads arrive
        }
    }
    __syncthreads();

    // Prologue: fill all 6 stages (chunk t -> A cols t*512B, B cols t*64B).
    if (tid == 0) {
        for (int t = 0; t < NST; ++t) {
            mbar_expect_tx(mb + t * 16, ST);
            tma_ld_2d(sbase + t * ST,            &tma_a, t * 256,       o_base, mb + t * 16);
            tma_ld_2d(sbase + t * ST + 8192,     &tma_a, t * 256 + 128, o_base, mb + t * 16);
            tma_ld_2d(sbase + t * ST + A_ST,     &tma_b, t * 64,        0,      mb + t * 16);
        }
    }

    // Per-lane invariant offsets (within an 8KB A sub-tile / B stage).
    const int row0 = warp * 16 + g;
    const uint32_t oA0 = SWZ(row0 * 128 + tig * 16);
    const uint32_t oA1 = SWZ((row0 + 8) * 128 + tig * 16);
    const uint32_t oA2 = SWZ(row0 * 128 + 64 + tig * 16);
    const uint32_t oA3 = SWZ((row0 + 8) * 128 + 64 + tig * 16);
    uint32_t oB[4];
#pragma unroll
    for (int f = 0; f < 4; ++f)
        oB[f] = A_ST + (f * 8 + g) * 64 + tig * 4;   // +c*32 per sub; b1=+16

    uint32_t acc[4][4];
#pragma unroll
    for (int f = 0; f < 4; ++f)
#pragma unroll
        for (int r = 0; r < 4; ++r) acc[f][r] = 0u;

    int s = 0;
    uint32_t ph = 0;
#pragma unroll 1
    for (int t = 0; t < KCH; ++t) {
        mbar_wait(mb + s * 16, ph);
        const uint32_t base = sbase + s * ST;

#pragma unroll
        for (int c = 0; c < 2; ++c) {
            const uint32_t ab = base + c * 8192;
            uint32_t a[4];
            a[0] = ld_pack(ab + oA0);
            a[1] = ld_pack(ab + oA1);
            a[2] = ld_pack(ab + oA2);
            a[3] = ld_pack(ab + oA3);
#pragma unroll
            for (int f = 0; f < 4; ++f) {
                const uint32_t b0 = lds32(base + oB[f] + c * 32);
                const uint32_t b1 = lds32(base + oB[f] + c * 32 + 16);
                mma_s8(acc[f], a, b0, b1);
            }
        }

        mbar_arrive(mb + s * 16 + 8);
        if (tid == 0 && t < KCH - NST) {
            mbar_wait(mb + s * 16 + 8, ph);     // all 128 done with stage s
            mbar_expect_tx(mb + s * 16, ST);
            const int tn = t + NST;
            tma_ld_2d(base,          &tma_a, tn * 256,       o_base, mb + s * 16);
            tma_ld_2d(base + 8192,   &tma_a, tn * 256 + 128, o_base, mb + s * 16);
            tma_ld_2d(base + A_ST,   &tma_b, tn * 64,        0,      mb + s * 16);
        }
        if (++s == NST) { s = 0; ph ^= 1; }
    }

    // Epilogue (mapping validated in R15): frag f covers n = f*8+{g},
    // c0/c1 -> row g cols tig*2/+1 ; c2/c3 -> row g+8. Level pair: f, f+2.
    const int o0 = o_base + warp * 16 + g;
    const int o1 = o0 + 8;
    const float sc0 = scale[o0], bi0 = bias[o0];
    const float sc1 = scale[o1], bi1 = bias[o1];
#pragma unroll
    for (int f = 0; f < 2; ++f) {
#pragma unroll
        for (int j = 0; j < 2; ++j) {
            const int b  = f * 8 + tig * 2 + j;
            const float s1 = g_s[b], s2 = g_s[16 + b];
            const float v0 = s1 * (float)(int)acc[f][j]
                           + s2 * (float)(int)acc[f + 2][j];
            const float v1 = s1 * (float)(int)acc[f][j + 2]
                           + s2 * (float)(int)acc[f + 2][j + 2];
            out[b * OUT_F + o0] = sc0 * v0 + bi0;
            out[b * OUT_F + o1] = sc1 * v1 + bi1;
        }
    }
}

// ---------------- host ----------------
typedef CUresult (*TmaEncodeFn)(
    CUtensorMap*, CUtensorMapDataType, cuuint32_t, void*,
    const cuuint64_t*, const cuuint64_t*, const cuuint32_t*, const cuuint32_t*,
    CUtensorMapInterleave, CUtensorMapSwizzle, CUtensorMapL2promotion,
    CUtensorMapFloatOOBfill);

extern "C" void kernel_launch(void* const* d_in, const int* in_sizes, int n_in,
                              void* d_out, int out_size) {
    // metadata order: x (f32), weight_int8 (int32), weight_scale (f32), bias (f32)
    const float4* X     = (const float4*)d_in[0];
    void*         W     = (void*)d_in[1];
    const float*  scale = (const float*)d_in[2];
    const float*  bias  = (const float*)d_in[3];
    float*        out   = (float*)d_out;
    (void)in_sizes; (void)n_in; (void)out_size;

    void* bptr = nullptr;
    cudaGetSymbolAddress(&bptr, g_B);

    TmaEncodeFn enc = nullptr;
    cudaDriverEntryPointQueryResult qr;
    cudaGetDriverEntryPointByVersion("cuTensorMapEncodeTiled", (void**)&enc,
                                     12000, cudaEnableDefault, &qr);

    CUtensorMap ta, tb;
    {   // A: raw W bytes [16384, 11008], box [128, 64], SW128
        cuuint64_t dims[2]   = {(cuuint64_t)IN_F * 4, OUT_F};
        cuuint64_t stride[1] = {(cuuint64_t)IN_F * 4};
        cuuint32_t box[2]    = {128, MTILE};
        cuuint32_t es[2]     = {1, 1};
        enc(&ta, CU_TENSOR_MAP_DATA_TYPE_UINT8, 2, W, dims, stride, box, es,
            CU_TENSOR_MAP_INTERLEAVE_NONE, CU_TENSOR_MAP_SWIZZLE_128B,
            CU_TENSOR_MAP_L2_PROMOTION_L2_128B, CU_TENSOR_MAP_FLOAT_OOB_FILL_NONE);
    }
    {   // B: packed q [4096, 32], box [64, 32], no swizzle
        cuuint64_t dims[2]   = {IN_F, 32};
        cuuint64_t stride[1] = {IN_F};
        cuuint32_t box[2]    = {64, 32};
        cuuint32_t es[2]     = {1, 1};
        enc(&tb, CU_TENSOR_MAP_DATA_TYPE_UINT8, 2, bptr, dims, stride, box, es,
            CU_TENSOR_MAP_INTERLEAVE_NONE, CU_TENSOR_MAP_SWIZZLE_NONE,
            CU_TENSOR_MAP_L2_PROMOTION_L2_128B, CU_TENSOR_MAP_FLOAT_OOB_FILL_NONE);
    }

    prep_k<<<BATCH, 256>>>(X);

    cudaFuncSetAttribute(qgemm, cudaFuncAttributeMaxDynamicSharedMemorySize, SMEM_TOTAL);
    qgemm<<<OUT_F / MTILE, 128, SMEM_TOTAL>>>(ta, tb, scale, bias, out);
}